// round 10
// baseline (speedup 1.0000x reference)
#include <cuda_runtime.h>
#include <cstdint>
#include <cstddef>
#include <math.h>

#define B_TOTAL 512
#define T_LEN   256
#define HID     128
#define G4      512
#define WINDOW  8
#define ENCO    128
#define R_ROWS  4
#define NCTA    128
#define NTHR    512
#define K4_SM   24           // k-quads in smem: k 0..95 (group0: 0..11, group1: 12..23)
#define BT      (B_TOTAL * T_LEN)

typedef unsigned long long ull;

__device__ __forceinline__ ull ffma2(ull a, ull b, ull c) {
    ull d;
    asm("fma.rn.f32x2 %0, %1, %2, %3;" : "=l"(d) : "l"(a), "l"(b), "l"(c));
    return d;
}
__device__ __forceinline__ float lo32(ull v) { return __uint_as_float((unsigned)v); }
__device__ __forceinline__ float hi32(ull v) { return __uint_as_float((unsigned)(v >> 32)); }
__device__ __forceinline__ ull pack2(float a, float b) {
    return (ull)__float_as_uint(a) | ((ull)__float_as_uint(b) << 32);
}
__device__ __forceinline__ float sigf(float x) {
    return __fdividef(1.f, 1.f + __expf(-x));
}
__device__ __forceinline__ float tanhf_(float x) {
    return 1.f - __fdividef(2.f, 1.f + __expf(2.f * x));
}

struct Smem {
    ull   Wq[K4_SM][G4][2];        // 196608 B : W_hh k 0..95
    alignas(16) ull h2[R_ROWS][HID/2];   // 2048 B : hidden state (single buffer)
    float gp[2][R_ROWS][G4];       //  16384 B : gate partials per K-half
    float tout[R_ROWS][T_LEN];     //   4096 B
    float intv[R_ROWS][T_LEN];     //   4096 B
    float xv[R_ROWS][WINDOW][5];   //    640 B
    float red[R_ROWS][4];          //     64 B
    float Esm[R_ROWS];             //     16 B
    float stage[640];              //   2560 B (init only)
};                                 // ~226.5 KB

// fc1 weights as transposed pairs
__device__ ull g_fc1p[64 * HID];

__global__ void prep_fc1(const float* __restrict__ fc1_w) {
    int idx = blockIdx.x * blockDim.x + threadIdx.x;
    if (idx < 64 * HID) {
        int k2 = idx >> 7, u = idx & 127;
        g_fc1p[idx] = pack2(fc1_w[u * HID + 2 * k2], fc1_w[u * HID + 2 * k2 + 1]);
    }
}

// K-half dot: smem quads [KQ0, KQ0+12), register tail = h ull-pairs [TPBASE, TPBASE+8).
// All loop indices compile-time -> every smem address is base + immediate.
template<int KQ0, int TPBASE>
__device__ __forceinline__ void dot_half(const Smem* __restrict__ s, int c2,
                                         const ull (&wtA)[8], const ull (&wtB)[8],
                                         ull (&a)[8])
{
    const ulonglong2* hq0 = reinterpret_cast<const ulonglong2*>(s->h2[0]);
    const ulonglong2* hq1 = reinterpret_cast<const ulonglong2*>(s->h2[1]);
    const ulonglong2* hq2 = reinterpret_cast<const ulonglong2*>(s->h2[2]);
    const ulonglong2* hq3 = reinterpret_cast<const ulonglong2*>(s->h2[3]);
    #pragma unroll
    for (int j = 0; j < 12; ++j) {
        const int k4 = KQ0 + j;
        ulonglong2 w0 = *reinterpret_cast<const ulonglong2*>(&s->Wq[k4][c2][0]);
        ulonglong2 w1 = *reinterpret_cast<const ulonglong2*>(&s->Wq[k4][c2 + 256][0]);
        ulonglong2 h0 = hq0[k4], h1 = hq1[k4], h2 = hq2[k4], h3 = hq3[k4];
        a[0] = ffma2(w0.x, h0.x, a[0]);  a[0] = ffma2(w0.y, h0.y, a[0]);
        a[4] = ffma2(w1.x, h0.x, a[4]);  a[4] = ffma2(w1.y, h0.y, a[4]);
        a[1] = ffma2(w0.x, h1.x, a[1]);  a[1] = ffma2(w0.y, h1.y, a[1]);
        a[5] = ffma2(w1.x, h1.x, a[5]);  a[5] = ffma2(w1.y, h1.y, a[5]);
        a[2] = ffma2(w0.x, h2.x, a[2]);  a[2] = ffma2(w0.y, h2.y, a[2]);
        a[6] = ffma2(w1.x, h2.x, a[6]);  a[6] = ffma2(w1.y, h2.y, a[6]);
        a[3] = ffma2(w0.x, h3.x, a[3]);  a[3] = ffma2(w0.y, h3.y, a[3]);
        a[7] = ffma2(w1.x, h3.x, a[7]);  a[7] = ffma2(w1.y, h3.y, a[7]);
    }
    #pragma unroll
    for (int j = 0; j < 4; ++j) {
        const int hb = (TPBASE / 2) + j;   // ulonglong2 index into h row
        ulonglong2 h0 = hq0[hb], h1 = hq1[hb], h2 = hq2[hb], h3 = hq3[hb];
        ull wa0 = wtA[2*j], wb0 = wtA[2*j+1];
        ull wa1 = wtB[2*j], wb1 = wtB[2*j+1];
        a[0] = ffma2(wa0, h0.x, a[0]);  a[0] = ffma2(wb0, h0.y, a[0]);
        a[4] = ffma2(wa1, h0.x, a[4]);  a[4] = ffma2(wb1, h0.y, a[4]);
        a[1] = ffma2(wa0, h1.x, a[1]);  a[1] = ffma2(wb0, h1.y, a[1]);
        a[5] = ffma2(wa1, h1.x, a[5]);  a[5] = ffma2(wb1, h1.y, a[5]);
        a[2] = ffma2(wa0, h2.x, a[2]);  a[2] = ffma2(wb0, h2.y, a[2]);
        a[6] = ffma2(wa1, h2.x, a[6]);  a[6] = ffma2(wb1, h2.y, a[6]);
        a[3] = ffma2(wa0, h3.x, a[3]);  a[3] = ffma2(wb0, h3.y, a[3]);
        a[7] = ffma2(wa1, h3.x, a[7]);  a[7] = ffma2(wb1, h3.y, a[7]);
    }
}

__global__ __launch_bounds__(NTHR, 1)
void modnn_kernel(const float* __restrict__ X,
                  const float* __restrict__ W_ih, const float* __restrict__ W_hh,
                  const float* __restrict__ b_ih, const float* __restrict__ b_hh,
                  const float* __restrict__ fc1_b,
                  const float* __restrict__ fc2_w, const float* __restrict__ fc2_b,
                  const float* __restrict__ int1_w, const float* __restrict__ int1_b,
                  const float* __restrict__ int3_w, const float* __restrict__ int3_b,
                  const float* __restrict__ scale_w, const float* __restrict__ zone_w,
                  float* __restrict__ out)
{
    extern __shared__ char smem_raw[];
    Smem* s = reinterpret_cast<Smem*>(smem_raw);
    const int tid = threadIdx.x;
    const int b0  = blockIdx.x * R_ROWS;
    const int kh  = tid >> 8;        // K-half group: 0 or 1 (warp-uniform)
    const int c2  = tid & 255;       // my column base (cols c2 and c2+256)

    // ---- stage W_hh k=0..95 as [k4][col] 16B quads ----
    for (int idx = tid; idx < K4_SM * G4; idx += NTHR) {
        int k4 = idx >> 9, col = idx & 511;
        const float* wr = W_hh + (size_t)col * HID + 4 * k4;
        s->Wq[k4][col][0] = pack2(wr[0], wr[1]);
        s->Wq[k4][col][1] = pack2(wr[2], wr[3]);
    }
    // int-module staging
    for (int idx = tid; idx < HID * 3; idx += NTHR) s->stage[idx] = int1_w[idx];
    for (int idx = tid; idx < HID; idx += NTHR) {
        s->stage[384 + idx] = int1_b[idx];
        s->stage[512 + idx] = int3_w[idx];
    }

    // ---- per-thread invariants ----
    float wihA[5], wihB[5];
    #pragma unroll
    for (int j = 0; j < 5; ++j) {
        wihA[j] = W_ih[c2 * 5 + j];
        wihB[j] = W_ih[(c2 + 256) * 5 + j];
    }
    const float btA = b_ih[c2] + b_hh[c2];
    const float btB = b_ih[c2 + 256] + b_hh[c2 + 256];

    // register tail: 8 pairs for each of my 2 columns (k-pairs [48+8kh, 56+8kh))
    ull wtA[8], wtB[8];
    {
        const int tp = 48 + kh * 8;
        const ull* pA = reinterpret_cast<const ull*>(W_hh + (size_t)c2 * HID) + tp;
        const ull* pB = reinterpret_cast<const ull*>(W_hh + (size_t)(c2 + 256) * HID) + tp;
        #pragma unroll
        for (int j = 0; j < 8; ++j) { wtA[j] = pA[j]; wtB[j] = pB[j]; }
    }

    // phase-2 mapping: thread <-> (row r2, unit u2)
    const int r2 = tid >> 7;
    const int u2 = tid & 127;
    const float b1r  = fc1_b[u2];
    const float w2r  = fc2_w[u2];
    const float zone = zone_w[0];
    const float fcb2 = fc2_b[0];
    const float i3b  = int3_b[0];
    const float scl  = scale_w[0];
    __syncthreads();

    // ---- precompute int_all; emit constant outputs; init tout/h/Esm ----
    {
        const float* tmp = s->stage;
        for (int it = tid; it < R_ROWS * T_LEN; it += NTHR) {
            int rr = it >> 8, tt = it & 255;
            const float* Xb = X + (size_t)(b0 + rr) * (T_LEN * 7) + tt * 7;
            float x0 = Xb[3], x1 = Xb[4], x2 = Xb[5];
            float acc = 0.f;
            #pragma unroll 8
            for (int uu = 0; uu < HID; ++uu) {
                float v = fmaf(tmp[uu*3], x0, fmaf(tmp[uu*3+1], x1, fmaf(tmp[uu*3+2], x2, tmp[384+uu])));
                v = fmaxf(v, 0.f);
                acc = fmaf(v, tmp[512 + uu], acc);
            }
            float val = scl * (1.f / (1.f + expf(-(acc + i3b))));
            s->intv[rr][tt] = val;
            size_t base = (size_t)(b0 + rr) * T_LEN + tt;
            out[(size_t)BT + base]   = Xb[6];                          // HVAC_list
            out[3*(size_t)BT + base] = (tt >= WINDOW) ? val : 0.f;     // Int_list
            if (tt < WINDOW) {
                out[base]                = Xb[0];                      // TOut[:, :w]
                out[2*(size_t)BT + base] = 0.f;                        // Ext zeros
                s->tout[rr][tt] = Xb[0];
            }
        }
        for (int idx = tid; idx < R_ROWS * (HID/2); idx += NTHR)
            s->h2[idx >> 6][idx & 63] = pack2(1.f, 1.f);
        if (tid < R_ROWS)
            s->Esm[tid] = X[(size_t)(b0 + tid) * (T_LEN * 7) + WINDOW * 7];
    }
    float cst = 1.f;   // cell state for (r2, u2)
    __syncthreads();

    // ================= main sequential time loop =================
    for (int i = WINDOW; i < T_LEN; ++i) {
        const bool  enc   = (i < ENCO);
        const float ratio = enc ? (float)i * (1.f / ENCO) : 0.f;

        // ---- window build (32 threads) ----
        if (tid < R_ROWS * WINDOW) {
            int rr = tid >> 3, tt = tid & 7;
            int pos = i - (WINDOW - 1) + tt;
            const float* Xb = X + (size_t)(b0 + rr) * (T_LEN * 7);
            float TO;
            if (tt == WINDOW - 1) {
                TO = s->Esm[rr];
                s->tout[rr][i] = TO;
                out[(size_t)(b0 + rr) * T_LEN + i] = TO;
            } else {
                TO = s->tout[rr][pos];
            }
            float e0 = enc ? fmaf(Xb[pos * 7], ratio, TO * (1.f - ratio)) : TO;
            s->xv[rr][tt][0] = e0;
            #pragma unroll
            for (int j = 1; j < 5; ++j) s->xv[rr][tt][j] = Xb[pos * 7 + j];
        }
        __syncthreads();

        // ---- 8 LSTM sub-steps, 2 barriers each ----
        #pragma unroll 1
        for (int st = 0; st < WINDOW; ++st) {
            // partial dots for cols c2, c2+256, rows 0..3, over my K-half
            float init0[R_ROWS], init1[R_ROWS];
            if (kh == 0) {
                #pragma unroll
                for (int r = 0; r < R_ROWS; ++r) {
                    float v0 = btA, v1 = btB;
                    #pragma unroll
                    for (int j = 0; j < 5; ++j) {
                        float xj = s->xv[r][st][j];
                        v0 = fmaf(xj, wihA[j], v0);
                        v1 = fmaf(xj, wihB[j], v1);
                    }
                    init0[r] = v0; init1[r] = v1;
                }
            } else {
                #pragma unroll
                for (int r = 0; r < R_ROWS; ++r) { init0[r] = 0.f; init1[r] = 0.f; }
            }

            ull a[8] = {0, 0, 0, 0, 0, 0, 0, 0};
            if (kh == 0) dot_half<0, 48>(s, c2, wtA, wtB, a);
            else         dot_half<12, 56>(s, c2, wtA, wtB, a);

            s->gp[kh][0][c2]       = init0[0] + lo32(a[0]) + hi32(a[0]);
            s->gp[kh][1][c2]       = init0[1] + lo32(a[1]) + hi32(a[1]);
            s->gp[kh][2][c2]       = init0[2] + lo32(a[2]) + hi32(a[2]);
            s->gp[kh][3][c2]       = init0[3] + lo32(a[3]) + hi32(a[3]);
            s->gp[kh][0][c2 + 256] = init1[0] + lo32(a[4]) + hi32(a[4]);
            s->gp[kh][1][c2 + 256] = init1[1] + lo32(a[5]) + hi32(a[5]);
            s->gp[kh][2][c2 + 256] = init1[2] + lo32(a[6]) + hi32(a[6]);
            s->gp[kh][3][c2 + 256] = init1[3] + lo32(a[7]) + hi32(a[7]);
            __syncthreads();

            // phase 2: thread-local c/h for (r2, u2)
            {
                float gi = s->gp[0][r2][u2]       + s->gp[1][r2][u2];
                float gf = s->gp[0][r2][u2 + 128] + s->gp[1][r2][u2 + 128];
                float gg = s->gp[0][r2][u2 + 256] + s->gp[1][r2][u2 + 256];
                float go = s->gp[0][r2][u2 + 384] + s->gp[1][r2][u2 + 384];
                cst = sigf(gf) * cst + sigf(gi) * tanhf_(gg);
                float hv = sigf(go) * tanhf_(cst);
                reinterpret_cast<float*>(&s->h2[0][0])[r2 * HID + u2] = hv;
            }
            __syncthreads();
        }

        // ---- ext head (first 256 threads, 2 rows each) ----
        if (kh == 0) {
            const int rA = r2;            // 0 or 1 (since tid < 256)
            const ull* hA = s->h2[rA];
            const ull* hB = s->h2[rA + 2];
            ull A0 = 0, A1 = 0;
            #pragma unroll 8
            for (int k2 = 0; k2 < 64; ++k2) {
                ull w = __ldg(&g_fc1p[k2 * HID + u2]);
                A0 = ffma2(w, hA[k2], A0);
                A1 = ffma2(w, hB[k2], A1);
            }
            float p0 = fmaxf(lo32(A0) + hi32(A0) + b1r, 0.f) * w2r;
            float p1 = fmaxf(lo32(A1) + hi32(A1) + b1r, 0.f) * w2r;
            #pragma unroll
            for (int m = 16; m > 0; m >>= 1) {
                p0 += __shfl_xor_sync(0xFFFFFFFFu, p0, m);
                p1 += __shfl_xor_sync(0xFFFFFFFFu, p1, m);
            }
            if ((tid & 31) == 0) {
                int w8 = tid >> 5;                 // 0..7
                s->red[rA][w8 & 3]     = p0;
                s->red[rA + 2][w8 & 3] = p1;
            }
        }
        __syncthreads();

        // ---- scalar tail ----
        if (tid < R_ROWS) {
            int rr = tid;
            float dot = s->red[rr][0] + s->red[rr][1] + s->red[rr][2] + s->red[rr][3];
            float ext = dot + fcb2;
            const float* Xb = X + (size_t)(b0 + rr) * (T_LEN * 7);
            float hv = Xb[i * 7 + 6];
            float it = s->intv[rr][i];
            float total = ext + hv + it;
            out[2*(size_t)BT + (size_t)(b0 + rr) * T_LEN + i] = ext;
            float E = s->Esm[rr];
            if (enc) E = ratio * Xb[i * 7] + (1.f - ratio) * E + total * zone;
            else     E = total * zone + E;
            s->Esm[rr] = E;
        }
        __syncthreads();
    }
}

extern "C" void kernel_launch(void* const* d_in, const int* in_sizes, int n_in,
                              void* d_out, int out_size) {
    const float* X       = (const float*)d_in[0];
    const float* W_ih    = (const float*)d_in[1];
    const float* W_hh    = (const float*)d_in[2];
    const float* b_ih    = (const float*)d_in[3];
    const float* b_hh    = (const float*)d_in[4];
    const float* fc1_w   = (const float*)d_in[5];
    const float* fc1_b   = (const float*)d_in[6];
    const float* fc2_w   = (const float*)d_in[7];
    const float* fc2_b   = (const float*)d_in[8];
    const float* int1_w  = (const float*)d_in[9];
    const float* int1_b  = (const float*)d_in[10];
    const float* int3_w  = (const float*)d_in[11];
    const float* int3_b  = (const float*)d_in[12];
    const float* scale_w = (const float*)d_in[13];
    const float* zone_w  = (const float*)d_in[14];
    float* out = (float*)d_out;

    prep_fc1<<<64, 128>>>(fc1_w);

    size_t smem = sizeof(Smem);
    cudaFuncSetAttribute(modnn_kernel, cudaFuncAttributeMaxDynamicSharedMemorySize, (int)smem);
    modnn_kernel<<<NCTA, NTHR, smem>>>(X, W_ih, W_hh, b_ih, b_hh,
                                       fc1_b, fc2_w, fc2_b,
                                       int1_w, int1_b, int3_w, int3_b,
                                       scale_w, zone_w, out);
}

// round 12
// speedup vs baseline: 1.0021x; 1.0021x over previous
#include <cuda_runtime.h>
#include <cstdint>
#include <cstddef>
#include <math.h>

#define B_TOTAL 512
#define T_LEN   256
#define HID     128
#define G4      512
#define WINDOW  8
#define ENCO    128
#define R_ROWS  4
#define NCTA    128
#define NTHR    512
#define K4_SM   24           // k-quads in smem: k 0..95 (group0: 0..11, group1: 12..23)
#define BT      (B_TOTAL * T_LEN)

typedef unsigned long long ull;

__device__ __forceinline__ ull ffma2(ull a, ull b, ull c) {
    ull d;
    asm("fma.rn.f32x2 %0, %1, %2, %3;" : "=l"(d) : "l"(a), "l"(b), "l"(c));
    return d;
}
__device__ __forceinline__ float lo32(ull v) { return __uint_as_float((unsigned)v); }
__device__ __forceinline__ float hi32(ull v) { return __uint_as_float((unsigned)(v >> 32)); }
__device__ __forceinline__ ull pack2(float a, float b) {
    return (ull)__float_as_uint(a) | ((ull)__float_as_uint(b) << 32);
}
__device__ __forceinline__ float sigf(float x) {
    return __fdividef(1.f, 1.f + __expf(-x));
}
__device__ __forceinline__ float tanhf_(float x) {
    return 1.f - __fdividef(2.f, 1.f + __expf(2.f * x));
}

struct Smem {
    ull   Wq[K4_SM][G4][2];        // 196608 B : W_hh k 0..95
    alignas(16) ull h2[R_ROWS][HID/2];   // 2048 B : hidden state (single buffer)
    float gp[2][R_ROWS][G4];       //  16384 B : gate partials per K-half
    float tout[R_ROWS][T_LEN];     //   4096 B
    float intv[R_ROWS][T_LEN];     //   4096 B
    float xv[R_ROWS][WINDOW][5];   //    640 B
    float red[R_ROWS][4];          //     64 B
    float Esm[R_ROWS];             //     16 B
    float stage[640];              //   2560 B (init only)
};                                 // ~226.5 KB

// fc1 weights as transposed pairs
__device__ ull g_fc1p[64 * HID];

__global__ void prep_fc1(const float* __restrict__ fc1_w) {
    int idx = blockIdx.x * blockDim.x + threadIdx.x;
    if (idx < 64 * HID) {
        int k2 = idx >> 7, u = idx & 127;
        g_fc1p[idx] = pack2(fc1_w[u * HID + 2 * k2], fc1_w[u * HID + 2 * k2 + 1]);
    }
}

// K-half dot: smem quads [KQ0, KQ0+12), register tail = h ull-pairs [TPBASE, TPBASE+8).
// Smem loop partially unrolled (affine indices stay base+immediate); tail fully
// unrolled so weight arrays keep static indices (register residency).
template<int KQ0, int TPBASE>
__device__ __forceinline__ void dot_half(const Smem* __restrict__ s, int c2,
                                         const ull (&wtA)[8], const ull (&wtB)[8],
                                         ull (&a)[8])
{
    const ulonglong2* hq0 = reinterpret_cast<const ulonglong2*>(s->h2[0]);
    const ulonglong2* hq1 = reinterpret_cast<const ulonglong2*>(s->h2[1]);
    const ulonglong2* hq2 = reinterpret_cast<const ulonglong2*>(s->h2[2]);
    const ulonglong2* hq3 = reinterpret_cast<const ulonglong2*>(s->h2[3]);
    #pragma unroll 4
    for (int j = 0; j < 12; ++j) {
        const int k4 = KQ0 + j;
        ulonglong2 w0 = *reinterpret_cast<const ulonglong2*>(&s->Wq[k4][c2][0]);
        ulonglong2 w1 = *reinterpret_cast<const ulonglong2*>(&s->Wq[k4][c2 + 256][0]);
        ulonglong2 h0 = hq0[k4], h1 = hq1[k4], h2 = hq2[k4], h3 = hq3[k4];
        a[0] = ffma2(w0.x, h0.x, a[0]);  a[0] = ffma2(w0.y, h0.y, a[0]);
        a[4] = ffma2(w1.x, h0.x, a[4]);  a[4] = ffma2(w1.y, h0.y, a[4]);
        a[1] = ffma2(w0.x, h1.x, a[1]);  a[1] = ffma2(w0.y, h1.y, a[1]);
        a[5] = ffma2(w1.x, h1.x, a[5]);  a[5] = ffma2(w1.y, h1.y, a[5]);
        a[2] = ffma2(w0.x, h2.x, a[2]);  a[2] = ffma2(w0.y, h2.y, a[2]);
        a[6] = ffma2(w1.x, h2.x, a[6]);  a[6] = ffma2(w1.y, h2.y, a[6]);
        a[3] = ffma2(w0.x, h3.x, a[3]);  a[3] = ffma2(w0.y, h3.y, a[3]);
        a[7] = ffma2(w1.x, h3.x, a[7]);  a[7] = ffma2(w1.y, h3.y, a[7]);
    }
    #pragma unroll
    for (int j = 0; j < 4; ++j) {
        const int hb = (TPBASE / 2) + j;   // ulonglong2 index into h row
        ulonglong2 h0 = hq0[hb], h1 = hq1[hb], h2 = hq2[hb], h3 = hq3[hb];
        ull wa0 = wtA[2*j], wb0 = wtA[2*j+1];
        ull wa1 = wtB[2*j], wb1 = wtB[2*j+1];
        a[0] = ffma2(wa0, h0.x, a[0]);  a[0] = ffma2(wb0, h0.y, a[0]);
        a[4] = ffma2(wa1, h0.x, a[4]);  a[4] = ffma2(wb1, h0.y, a[4]);
        a[1] = ffma2(wa0, h1.x, a[1]);  a[1] = ffma2(wb0, h1.y, a[1]);
        a[5] = ffma2(wa1, h1.x, a[5]);  a[5] = ffma2(wb1, h1.y, a[5]);
        a[2] = ffma2(wa0, h2.x, a[2]);  a[2] = ffma2(wb0, h2.y, a[2]);
        a[6] = ffma2(wa1, h2.x, a[6]);  a[6] = ffma2(wb1, h2.y, a[6]);
        a[3] = ffma2(wa0, h3.x, a[3]);  a[3] = ffma2(wb0, h3.y, a[3]);
        a[7] = ffma2(wa1, h3.x, a[7]);  a[7] = ffma2(wb1, h3.y, a[7]);
    }
}

__global__ __launch_bounds__(NTHR, 1)
void modnn_kernel(const float* __restrict__ X,
                  const float* __restrict__ W_ih, const float* __restrict__ W_hh,
                  const float* __restrict__ b_ih, const float* __restrict__ b_hh,
                  const float* __restrict__ fc1_b,
                  const float* __restrict__ fc2_w, const float* __restrict__ fc2_b,
                  const float* __restrict__ int1_w, const float* __restrict__ int1_b,
                  const float* __restrict__ int3_w, const float* __restrict__ int3_b,
                  const float* __restrict__ scale_w, const float* __restrict__ zone_w,
                  float* __restrict__ out)
{
    extern __shared__ char smem_raw[];
    Smem* s = reinterpret_cast<Smem*>(smem_raw);
    const int tid = threadIdx.x;
    const int b0  = blockIdx.x * R_ROWS;
    const int kh  = tid >> 8;        // K-half group: 0 or 1 (warp-uniform)
    const int c2  = tid & 255;       // my column base (cols c2 and c2+256)

    // ---- stage W_hh k=0..95 as [k4][col] 16B quads ----
    for (int idx = tid; idx < K4_SM * G4; idx += NTHR) {
        int k4 = idx >> 9, col = idx & 511;
        const float* wr = W_hh + (size_t)col * HID + 4 * k4;
        s->Wq[k4][col][0] = pack2(wr[0], wr[1]);
        s->Wq[k4][col][1] = pack2(wr[2], wr[3]);
    }
    // int-module staging
    for (int idx = tid; idx < HID * 3; idx += NTHR) s->stage[idx] = int1_w[idx];
    for (int idx = tid; idx < HID; idx += NTHR) {
        s->stage[384 + idx] = int1_b[idx];
        s->stage[512 + idx] = int3_w[idx];
    }

    // ---- per-thread invariants (x-part weights only for kh==0 group) ----
    float wihA[5], wihB[5];
    float btA = 0.f, btB = 0.f;
    if (kh == 0) {
        #pragma unroll
        for (int j = 0; j < 5; ++j) {
            wihA[j] = W_ih[c2 * 5 + j];
            wihB[j] = W_ih[(c2 + 256) * 5 + j];
        }
        btA = b_ih[c2] + b_hh[c2];
        btB = b_ih[c2 + 256] + b_hh[c2 + 256];
    }

    // register tail: 8 pairs for each of my 2 columns (k-pairs [48+8kh, 56+8kh))
    ull wtA[8], wtB[8];
    {
        const int tp = 48 + kh * 8;
        const ull* pA = reinterpret_cast<const ull*>(W_hh + (size_t)c2 * HID) + tp;
        const ull* pB = reinterpret_cast<const ull*>(W_hh + (size_t)(c2 + 256) * HID) + tp;
        #pragma unroll
        for (int j = 0; j < 8; ++j) { wtA[j] = pA[j]; wtB[j] = pB[j]; }
    }

    // phase-2 mapping: thread <-> (row r2, unit u2)
    const int r2 = tid >> 7;
    const int u2 = tid & 127;
    const float b1r  = fc1_b[u2];
    const float w2r  = fc2_w[u2];
    const float zone = zone_w[0];
    const float fcb2 = fc2_b[0];
    const float i3b  = int3_b[0];
    const float scl  = scale_w[0];
    __syncthreads();

    // ---- precompute int_all; emit constant outputs; init tout/h/Esm ----
    {
        const float* tmp = s->stage;
        for (int it = tid; it < R_ROWS * T_LEN; it += NTHR) {
            int rr = it >> 8, tt = it & 255;
            const float* Xb = X + (size_t)(b0 + rr) * (T_LEN * 7) + tt * 7;
            float x0 = Xb[3], x1 = Xb[4], x2 = Xb[5];
            float acc = 0.f;
            #pragma unroll 8
            for (int uu = 0; uu < HID; ++uu) {
                float v = fmaf(tmp[uu*3], x0, fmaf(tmp[uu*3+1], x1, fmaf(tmp[uu*3+2], x2, tmp[384+uu])));
                v = fmaxf(v, 0.f);
                acc = fmaf(v, tmp[512 + uu], acc);
            }
            float val = scl * (1.f / (1.f + expf(-(acc + i3b))));
            s->intv[rr][tt] = val;
            size_t base = (size_t)(b0 + rr) * T_LEN + tt;
            out[(size_t)BT + base]   = Xb[6];                          // HVAC_list
            out[3*(size_t)BT + base] = (tt >= WINDOW) ? val : 0.f;     // Int_list
            if (tt < WINDOW) {
                out[base]                = Xb[0];                      // TOut[:, :w]
                out[2*(size_t)BT + base] = 0.f;                        // Ext zeros
                s->tout[rr][tt] = Xb[0];
            }
        }
        for (int idx = tid; idx < R_ROWS * (HID/2); idx += NTHR)
            s->h2[idx >> 6][idx & 63] = pack2(1.f, 1.f);
        if (tid < R_ROWS)
            s->Esm[tid] = X[(size_t)(b0 + tid) * (T_LEN * 7) + WINDOW * 7];
    }
    float cst = 1.f;   // cell state for (r2, u2)
    __syncthreads();

    // ================= main sequential time loop =================
    for (int i = WINDOW; i < T_LEN; ++i) {
        const bool  enc   = (i < ENCO);
        const float ratio = enc ? (float)i * (1.f / ENCO) : 0.f;

        // ---- window build (32 threads) ----
        if (tid < R_ROWS * WINDOW) {
            int rr = tid >> 3, tt = tid & 7;
            int pos = i - (WINDOW - 1) + tt;
            const float* Xb = X + (size_t)(b0 + rr) * (T_LEN * 7);
            float TO;
            if (tt == WINDOW - 1) {
                TO = s->Esm[rr];
                s->tout[rr][i] = TO;
                out[(size_t)(b0 + rr) * T_LEN + i] = TO;
            } else {
                TO = s->tout[rr][pos];
            }
            float e0 = enc ? fmaf(Xb[pos * 7], ratio, TO * (1.f - ratio)) : TO;
            s->xv[rr][tt][0] = e0;
            #pragma unroll
            for (int j = 1; j < 5; ++j) s->xv[rr][tt][j] = Xb[pos * 7 + j];
        }
        __syncthreads();

        // ---- 8 LSTM sub-steps, 2 barriers each ----
        #pragma unroll 1
        for (int st = 0; st < WINDOW; ++st) {
            // dot product over my K-half first (x-part computed after, to
            // shorten the live range of its registers)
            ull a[8] = {0, 0, 0, 0, 0, 0, 0, 0};
            if (kh == 0) dot_half<0, 48>(s, c2, wtA, wtB, a);
            else         dot_half<12, 56>(s, c2, wtA, wtB, a);

            float init0[R_ROWS], init1[R_ROWS];
            if (kh == 0) {
                #pragma unroll
                for (int r = 0; r < R_ROWS; ++r) {
                    float v0 = btA, v1 = btB;
                    #pragma unroll
                    for (int j = 0; j < 5; ++j) {
                        float xj = s->xv[r][st][j];
                        v0 = fmaf(xj, wihA[j], v0);
                        v1 = fmaf(xj, wihB[j], v1);
                    }
                    init0[r] = v0; init1[r] = v1;
                }
            } else {
                #pragma unroll
                for (int r = 0; r < R_ROWS; ++r) { init0[r] = 0.f; init1[r] = 0.f; }
            }

            s->gp[kh][0][c2]       = init0[0] + lo32(a[0]) + hi32(a[0]);
            s->gp[kh][1][c2]       = init0[1] + lo32(a[1]) + hi32(a[1]);
            s->gp[kh][2][c2]       = init0[2] + lo32(a[2]) + hi32(a[2]);
            s->gp[kh][3][c2]       = init0[3] + lo32(a[3]) + hi32(a[3]);
            s->gp[kh][0][c2 + 256] = init1[0] + lo32(a[4]) + hi32(a[4]);
            s->gp[kh][1][c2 + 256] = init1[1] + lo32(a[5]) + hi32(a[5]);
            s->gp[kh][2][c2 + 256] = init1[2] + lo32(a[6]) + hi32(a[6]);
            s->gp[kh][3][c2 + 256] = init1[3] + lo32(a[7]) + hi32(a[7]);
            __syncthreads();

            // phase 2: thread-local c/h for (r2, u2)
            {
                float gi = s->gp[0][r2][u2]       + s->gp[1][r2][u2];
                float gf = s->gp[0][r2][u2 + 128] + s->gp[1][r2][u2 + 128];
                float gg = s->gp[0][r2][u2 + 256] + s->gp[1][r2][u2 + 256];
                float go = s->gp[0][r2][u2 + 384] + s->gp[1][r2][u2 + 384];
                cst = sigf(gf) * cst + sigf(gi) * tanhf_(gg);
                float hv = sigf(go) * tanhf_(cst);
                reinterpret_cast<float*>(&s->h2[0][0])[r2 * HID + u2] = hv;
            }
            __syncthreads();
        }

        // ---- ext head (first 256 threads, 2 rows each) ----
        if (kh == 0) {
            const int rA = r2;            // 0 or 1 (since tid < 256)
            const ull* hA = s->h2[rA];
            const ull* hB = s->h2[rA + 2];
            ull A0 = 0, A1 = 0;
            #pragma unroll 8
            for (int k2 = 0; k2 < 64; ++k2) {
                ull w = __ldg(&g_fc1p[k2 * HID + u2]);
                A0 = ffma2(w, hA[k2], A0);
                A1 = ffma2(w, hB[k2], A1);
            }
            float p0 = fmaxf(lo32(A0) + hi32(A0) + b1r, 0.f) * w2r;
            float p1 = fmaxf(lo32(A1) + hi32(A1) + b1r, 0.f) * w2r;
            #pragma unroll
            for (int m = 16; m > 0; m >>= 1) {
                p0 += __shfl_xor_sync(0xFFFFFFFFu, p0, m);
                p1 += __shfl_xor_sync(0xFFFFFFFFu, p1, m);
            }
            if ((tid & 31) == 0) {
                int w8 = tid >> 5;                 // 0..7
                s->red[rA][w8 & 3]     = p0;
                s->red[rA + 2][w8 & 3] = p1;
            }
        }
        __syncthreads();

        // ---- scalar tail ----
        if (tid < R_ROWS) {
            int rr = tid;
            float dot = s->red[rr][0] + s->red[rr][1] + s->red[rr][2] + s->red[rr][3];
            float ext = dot + fcb2;
            const float* Xb = X + (size_t)(b0 + rr) * (T_LEN * 7);
            float hv = Xb[i * 7 + 6];
            float it = s->intv[rr][i];
            float total = ext + hv + it;
            out[2*(size_t)BT + (size_t)(b0 + rr) * T_LEN + i] = ext;
            float E = s->Esm[rr];
            if (enc) E = ratio * Xb[i * 7] + (1.f - ratio) * E + total * zone;
            else     E = total * zone + E;
            s->Esm[rr] = E;
        }
        __syncthreads();
    }
}

extern "C" void kernel_launch(void* const* d_in, const int* in_sizes, int n_in,
                              void* d_out, int out_size) {
    const float* X       = (const float*)d_in[0];
    const float* W_ih    = (const float*)d_in[1];
    const float* W_hh    = (const float*)d_in[2];
    const float* b_ih    = (const float*)d_in[3];
    const float* b_hh    = (const float*)d_in[4];
    const float* fc1_w   = (const float*)d_in[5];
    const float* fc1_b   = (const float*)d_in[6];
    const float* fc2_w   = (const float*)d_in[7];
    const float* fc2_b   = (const float*)d_in[8];
    const float* int1_w  = (const float*)d_in[9];
    const float* int1_b  = (const float*)d_in[10];
    const float* int3_w  = (const float*)d_in[11];
    const float* int3_b  = (const float*)d_in[12];
    const float* scale_w = (const float*)d_in[13];
    const float* zone_w  = (const float*)d_in[14];
    float* out = (float*)d_out;

    prep_fc1<<<64, 128>>>(fc1_w);

    size_t smem = sizeof(Smem);
    cudaFuncSetAttribute(modnn_kernel, cudaFuncAttributeMaxDynamicSharedMemorySize, (int)smem);
    modnn_kernel<<<NCTA, NTHR, smem>>>(X, W_ih, W_hh, b_ih, b_hh,
                                       fc1_b, fc2_w, fc2_b,
                                       int1_w, int1_b, int3_w, int3_b,
                                       scale_w, zone_w, out);
}